// round 16
// baseline (speedup 1.0000x reference)
#include <cuda_runtime.h>
#include <cstdint>

// LIF recurrence over 4 timesteps (forward value only):
//   mem = 0.25*mem + x[t]; spike = mem > 0.5; out[t] = spike; mem = spike ? 0 : mem
//
// x/out: [T=4, N=8388608] fp32. At the HBM streaming roofline (~7.23 TB/s
// app-effective, 90.4% of 8 TB/s spec, 1:1 R/W mix). Measured optimum base
// (R10): fused kernel, v8 ld/st, loads ld.global.nc.cs, stores st.global.wt,
// blk 256, flat grid.
// R15: loads stay front-batched, but each store issues IMMEDIATELY after its
// timestep's compute (store(t) depends only on spike(t)). The volatile-asm
// memory clobbers previously pinned all stores after the full compute phase;
// interleaving starts each thread's write stream ~40 cycles earlier, smoothing
// the per-warp R->W transition on the saturated bus.

static constexpr float DECAY  = 0.25f;
static constexpr float THRESH = 0.5f;   // V_TH=1: mem/V_TH > 0.5 <=> mem > 0.5

struct f8 { float v[8]; };

__device__ __forceinline__ f8 ldg256_nc_cs(const float* p) {
    f8 r;
    asm volatile(
        "ld.global.nc.cs.v8.f32 {%0,%1,%2,%3,%4,%5,%6,%7}, [%8];"
        : "=f"(r.v[0]), "=f"(r.v[1]), "=f"(r.v[2]), "=f"(r.v[3]),
          "=f"(r.v[4]), "=f"(r.v[5]), "=f"(r.v[6]), "=f"(r.v[7])
        : "l"(p));
    return r;
}

__device__ __forceinline__ void stg256_wt(float* p, const f8& r) {
    asm volatile(
        "st.global.wt.v8.f32 [%0], {%1,%2,%3,%4,%5,%6,%7,%8};"
        :: "l"(p),
           "f"(r.v[0]), "f"(r.v[1]), "f"(r.v[2]), "f"(r.v[3]),
           "f"(r.v[4]), "f"(r.v[5]), "f"(r.v[6]), "f"(r.v[7])
        : "memory");
}

__device__ __forceinline__ void lif_step(float& mem, const float x, float& sp) {
    mem = fmaf(mem, DECAY, x);
    bool s = mem > THRESH;
    sp  = s ? 1.f : 0.f;
    mem = s ? 0.f : mem;
}

__device__ __forceinline__ void lif_step8(f8& mem, f8& io /* in: x, out: spike */) {
    #pragma unroll
    for (int k = 0; k < 8; ++k)
        lif_step(mem.v[k], io.v[k], io.v[k]);
}

__global__ __launch_bounds__(256)
void lif_kernel(const float* __restrict__ x, float* __restrict__ out, int n8) {
    const int i = blockIdx.x * blockDim.x + threadIdx.x;
    if (i >= n8) return;

    const size_t e = (size_t)i * 8;          // element offset within a timestep
    const size_t n = (size_t)n8 * 8;         // elements per timestep

    // ---- read phase: all 4 256-bit nc loads issued up front (MLP=4) ----
    f8 v0 = ldg256_nc_cs(x + 0 * n + e);
    f8 v1 = ldg256_nc_cs(x + 1 * n + e);
    f8 v2 = ldg256_nc_cs(x + 2 * n + e);
    f8 v3 = ldg256_nc_cs(x + 3 * n + e);

    // ---- compute + store interleaved: store(t) right after step(t) ----
    f8 mem;
    #pragma unroll
    for (int k = 0; k < 8; ++k) mem.v[k] = 0.f;

    lif_step8(mem, v0);
    stg256_wt(out + 0 * n + e, v0);
    lif_step8(mem, v1);
    stg256_wt(out + 1 * n + e, v1);
    lif_step8(mem, v2);
    stg256_wt(out + 2 * n + e, v2);
    lif_step8(mem, v3);
    stg256_wt(out + 3 * n + e, v3);
}

extern "C" void kernel_launch(void* const* d_in, const int* in_sizes, int n_in,
                              void* d_out, int out_size) {
    const float* x = (const float*)d_in[0];
    float* out = (float*)d_out;

    const int total = in_sizes[0];          // T*N = 33,554,432
    const int n = total / 4;                // N per timestep = 8,388,608
    const int n8 = n / 8;                   // v8 groups per timestep = 1,048,576

    const int threads = 256;
    const int blocks = (n8 + threads - 1) / threads;   // 4096

    lif_kernel<<<blocks, threads>>>(x, out, n8);
}

// round 17
// speedup vs baseline: 1.0071x; 1.0071x over previous
#include <cuda_runtime.h>
#include <cstdint>

// LIF recurrence over 4 timesteps (forward value only):
//   mem = 0.25*mem + x[t]; spike = mem > 0.5; out[t] = spike; mem = spike ? 0 : mem
//
// x/out: [T=4, N=8388608] fp32.
//
// FINAL FORM (= R10/R14, best measured: 37.12us kernel, 45.06-45.25us bench,
// reproduced 3x). 7.23 TB/s app-effective = 90.4% of the 8 TB/s HBM spec on a
// 1:1 R/W stream; reads ~3.6 + writes ~3.6 TB/s concurrent, at the bus limit
// (pure-write directional ceiling measured at ~3.5 TB/s in R8).
//
// 13-variant search closed every lever:
//   - fused 1-kernel >> 2-pass bit-packed split (write ceiling + 2x replay cost)
//   - 256-bit v8 ld/st, ILP=1, batched read->compute->write
//     (ILP=2 regressed ~2%; interleaved stores neutral; f4 ~1.5% slower)
//   - loads  ld.global.nc.cs.v8  (read-only, zero-reuse)
//   - stores st.global.wt.v8     (> .cs > .wb)
//   - occ 41-84%, MLP 1-8, blk 256/512, flat/persistent grid: all neutral
//   - limiter: DRAM bus efficiency on the mixed stream; traffic (256 MiB) is
//     the contractual floor given fp32 I/O. Not reachable from SASS.

static constexpr float DECAY  = 0.25f;
static constexpr float THRESH = 0.5f;   // V_TH=1: mem/V_TH > 0.5 <=> mem > 0.5

struct f8 { float v[8]; };

__device__ __forceinline__ f8 ldg256_nc_cs(const float* p) {
    f8 r;
    asm volatile(
        "ld.global.nc.cs.v8.f32 {%0,%1,%2,%3,%4,%5,%6,%7}, [%8];"
        : "=f"(r.v[0]), "=f"(r.v[1]), "=f"(r.v[2]), "=f"(r.v[3]),
          "=f"(r.v[4]), "=f"(r.v[5]), "=f"(r.v[6]), "=f"(r.v[7])
        : "l"(p));
    return r;
}

__device__ __forceinline__ void stg256_wt(float* p, const f8& r) {
    asm volatile(
        "st.global.wt.v8.f32 [%0], {%1,%2,%3,%4,%5,%6,%7,%8};"
        :: "l"(p),
           "f"(r.v[0]), "f"(r.v[1]), "f"(r.v[2]), "f"(r.v[3]),
           "f"(r.v[4]), "f"(r.v[5]), "f"(r.v[6]), "f"(r.v[7])
        : "memory");
}

__device__ __forceinline__ void lif_step(float& mem, const float x, float& sp) {
    mem = fmaf(mem, DECAY, x);
    bool s = mem > THRESH;
    sp  = s ? 1.f : 0.f;
    mem = s ? 0.f : mem;
}

__device__ __forceinline__ void lif_step8(f8& mem, f8& io /* in: x, out: spike */) {
    #pragma unroll
    for (int k = 0; k < 8; ++k)
        lif_step(mem.v[k], io.v[k], io.v[k]);
}

__global__ __launch_bounds__(256)
void lif_kernel(const float* __restrict__ x, float* __restrict__ out, int n8) {
    const int i = blockIdx.x * blockDim.x + threadIdx.x;
    if (i >= n8) return;

    const size_t e = (size_t)i * 8;          // element offset within a timestep
    const size_t n = (size_t)n8 * 8;         // elements per timestep

    // ---- read phase: 4 independent 256-bit nc loads in flight ----
    f8 v0 = ldg256_nc_cs(x + 0 * n + e);
    f8 v1 = ldg256_nc_cs(x + 1 * n + e);
    f8 v2 = ldg256_nc_cs(x + 2 * n + e);
    f8 v3 = ldg256_nc_cs(x + 3 * n + e);

    // ---- compute: sequential recurrence in registers ----
    f8 mem;
    #pragma unroll
    for (int k = 0; k < 8; ++k) mem.v[k] = 0.f;
    lif_step8(mem, v0);
    lif_step8(mem, v1);
    lif_step8(mem, v2);
    lif_step8(mem, v3);

    // ---- write phase: batched 256-bit write-through stores ----
    stg256_wt(out + 0 * n + e, v0);
    stg256_wt(out + 1 * n + e, v1);
    stg256_wt(out + 2 * n + e, v2);
    stg256_wt(out + 3 * n + e, v3);
}

extern "C" void kernel_launch(void* const* d_in, const int* in_sizes, int n_in,
                              void* d_out, int out_size) {
    const float* x = (const float*)d_in[0];
    float* out = (float*)d_out;

    const int total = in_sizes[0];          // T*N = 33,554,432
    const int n = total / 4;                // N per timestep = 8,388,608
    const int n8 = n / 8;                   // v8 groups per timestep = 1,048,576

    const int threads = 256;
    const int blocks = (n8 + threads - 1) / threads;   // 4096

    lif_kernel<<<blocks, threads>>>(x, out, n8);
}